// round 2
// baseline (speedup 1.0000x reference)
#include <cuda_runtime.h>
#include <cuda_fp16.h>
#include <cstdint>

// Problem dims (fixed for this dataset entry)
// x: [B*S=16384, H=1024] fp32 ; conv_w: [L=20, H, H] ; norm_w: [H]
#define HDIM 1024
#define MDIM 16384

// Scratch (allocation-free rule: __device__ globals)
__device__ __half g_Wh[HDIM * HDIM];          // reduced weights, fp16, [o][i] (K-major)
__device__ __half g_xh[(size_t)MDIM * HDIM];  // x in fp16
__device__ float  g_y [(size_t)MDIM * HDIM];  // GEMM output (pre-norm)

// ---------------------------------------------------------------------------
// Kernel 1: W[o,i] = (sum_l conv_w[l,o,i]) / L   -> fp16
// ---------------------------------------------------------------------------
__global__ void reduce_w_kernel(const float4* __restrict__ w, int L, int HH4, float inv_l) {
    int idx = blockIdx.x * blockDim.x + threadIdx.x;
    if (idx >= HH4) return;
    float4 s = make_float4(0.f, 0.f, 0.f, 0.f);
    for (int l = 0; l < L; ++l) {
        float4 v = w[(size_t)l * HH4 + idx];
        s.x += v.x; s.y += v.y; s.z += v.z; s.w += v.w;
    }
    __half2* out = reinterpret_cast<__half2*>(g_Wh);
    out[2 * idx]     = __floats2half2_rn(s.x * inv_l, s.y * inv_l);
    out[2 * idx + 1] = __floats2half2_rn(s.z * inv_l, s.w * inv_l);
}

// ---------------------------------------------------------------------------
// Kernel 2: x fp32 -> fp16
// ---------------------------------------------------------------------------
__global__ void convert_x_kernel(const float4* __restrict__ x, int n4) {
    int idx = blockIdx.x * blockDim.x + threadIdx.x;
    if (idx >= n4) return;
    float4 v = x[idx];
    __half2* out = reinterpret_cast<__half2*>(g_xh);
    out[2 * idx]     = __floats2half2_rn(v.x, v.y);
    out[2 * idx + 1] = __floats2half2_rn(v.z, v.w);
}

// ---------------------------------------------------------------------------
// Kernel 3: GEMM  C[m,n] = sum_k A[m,k] * B[n,k]  (A=g_xh, B=g_Wh, C=g_y)
// 128x128x32 CTA tile, 8 warps (4x2), double-buffered cp.async, mma.m16n8k16
// ---------------------------------------------------------------------------
#define BM 128
#define BN 128
#define BK 32
#define SROW 40  // halfs per smem row (32 data + 8 pad -> 80B stride, conflict-free ldmatrix)

__device__ __forceinline__ void cp16(uint32_t sp, const void* gp) {
    asm volatile("cp.async.cg.shared.global [%0], [%1], 16;\n" :: "r"(sp), "l"(gp));
}

__device__ __forceinline__ void ldmx4(uint32_t& r0, uint32_t& r1, uint32_t& r2, uint32_t& r3,
                                      uint32_t addr) {
    asm volatile("ldmatrix.sync.aligned.m8n8.x4.shared.b16 {%0,%1,%2,%3}, [%4];"
                 : "=r"(r0), "=r"(r1), "=r"(r2), "=r"(r3) : "r"(addr));
}

__device__ __forceinline__ void mma16816(float* c, const uint32_t* a, const uint32_t* b) {
    asm volatile(
        "mma.sync.aligned.m16n8k16.row.col.f32.f16.f16.f32 "
        "{%0,%1,%2,%3}, {%4,%5,%6,%7}, {%8,%9}, {%0,%1,%2,%3};"
        : "+f"(c[0]), "+f"(c[1]), "+f"(c[2]), "+f"(c[3])
        : "r"(a[0]), "r"(a[1]), "r"(a[2]), "r"(a[3]), "r"(b[0]), "r"(b[1]));
}

__device__ __forceinline__ void load_tiles(__half* sA, __half* sB,
                                           const __half* __restrict__ A,
                                           const __half* __restrict__ Bm,
                                           int m0, int n0, int k0, int K, int tid) {
#pragma unroll
    for (int it = 0; it < 2; ++it) {
        int idx = tid + it * 256;
        int row = idx >> 2, cc = idx & 3;
        cp16((uint32_t)__cvta_generic_to_shared(&sA[row * SROW + cc * 8]),
             A + (size_t)(m0 + row) * K + k0 + cc * 8);
    }
#pragma unroll
    for (int it = 0; it < 2; ++it) {
        int idx = tid + it * 256;
        int row = idx >> 2, cc = idx & 3;
        cp16((uint32_t)__cvta_generic_to_shared(&sB[row * SROW + cc * 8]),
             Bm + (size_t)(n0 + row) * K + k0 + cc * 8);
    }
    asm volatile("cp.async.commit_group;\n" ::: "memory");
}

__global__ __launch_bounds__(256) void gemm_f16_kernel(int M, int N, int K) {
    const __half* A  = g_xh;
    const __half* Bm = g_Wh;
    float* C = g_y;

    __shared__ __half sA[2][BM * SROW];
    __shared__ __half sB[2][BN * SROW];

    const int tid  = threadIdx.x;
    const int lane = tid & 31;
    const int warp = tid >> 5;
    const int wm = warp >> 1;  // 0..3 : 32-row slab
    const int wn = warp & 1;   // 0..1 : 64-col slab
    const int m0 = blockIdx.y * BM;
    const int n0 = blockIdx.x * BN;

    float acc[2][8][4];
#pragma unroll
    for (int mt = 0; mt < 2; ++mt)
#pragma unroll
        for (int nt = 0; nt < 8; ++nt)
#pragma unroll
            for (int i = 0; i < 4; ++i) acc[mt][nt][i] = 0.f;

    const int KT = K / BK;  // 32

    load_tiles(sA[0], sB[0], A, Bm, m0, n0, 0, K, tid);
    load_tiles(sA[1], sB[1], A, Bm, m0, n0, BK, K, tid);
    asm volatile("cp.async.wait_group %0;\n" :: "n"(1) : "memory");
    __syncthreads();

    for (int kt = 0; kt < KT; ++kt) {
        const int s = kt & 1;
#pragma unroll
        for (int kk = 0; kk < 2; ++kk) {
            uint32_t afr[2][4];
#pragma unroll
            for (int mt = 0; mt < 2; ++mt) {
                int row = wm * 32 + mt * 16 + (lane & 15);
                int col = kk * 16 + (lane >> 4) * 8;
                uint32_t ad = (uint32_t)__cvta_generic_to_shared(&sA[s][row * SROW + col]);
                ldmx4(afr[mt][0], afr[mt][1], afr[mt][2], afr[mt][3], ad);
            }
            uint32_t bfr[8][2];
#pragma unroll
            for (int pj = 0; pj < 4; ++pj) {
                int row = wn * 64 + pj * 16 + (lane >> 4) * 8 + (lane & 7);
                int col = kk * 16 + ((lane >> 3) & 1) * 8;
                uint32_t ad = (uint32_t)__cvta_generic_to_shared(&sB[s][row * SROW + col]);
                uint32_t r0, r1, r2, r3;
                ldmx4(r0, r1, r2, r3, ad);
                bfr[2 * pj][0] = r0; bfr[2 * pj][1] = r1;
                bfr[2 * pj + 1][0] = r2; bfr[2 * pj + 1][1] = r3;
            }
#pragma unroll
            for (int mt = 0; mt < 2; ++mt)
#pragma unroll
                for (int nt = 0; nt < 8; ++nt)
                    mma16816(acc[mt][nt], afr[mt], bfr[nt]);
        }
        __syncthreads();
        if (kt + 2 < KT) load_tiles(sA[s], sB[s], A, Bm, m0, n0, (kt + 2) * BK, K, tid);
        if (kt + 1 < KT) {
            if (kt + 2 < KT)
                asm volatile("cp.async.wait_group %0;\n" :: "n"(1) : "memory");
            else
                asm volatile("cp.async.wait_group %0;\n" :: "n"(0) : "memory");
            __syncthreads();
        }
    }

    // Epilogue: write fp32 y
#pragma unroll
    for (int mt = 0; mt < 2; ++mt) {
#pragma unroll
        for (int nt = 0; nt < 8; ++nt) {
            int row = m0 + wm * 32 + mt * 16 + (lane >> 2);
            int col = n0 + wn * 64 + nt * 8 + (lane & 3) * 2;
            float2 v0 = make_float2(acc[mt][nt][0], acc[mt][nt][1]);
            float2 v1 = make_float2(acc[mt][nt][2], acc[mt][nt][3]);
            *reinterpret_cast<float2*>(&C[(size_t)row * N + col]) = v0;
            *reinterpret_cast<float2*>(&C[(size_t)(row + 8) * N + col]) = v1;
        }
    }
}

// ---------------------------------------------------------------------------
// Kernel 4: RMSNorm per row of 1024, one block per row, 256 threads
// ---------------------------------------------------------------------------
__global__ __launch_bounds__(256) void rmsnorm_kernel(const float4* __restrict__ nw,
                                                      float4* __restrict__ out) {
    const int row = blockIdx.x;
    const float4* yr = reinterpret_cast<const float4*>(g_y) + (size_t)row * (HDIM / 4);
    const int tid = threadIdx.x;

    float4 v = yr[tid];
    float s = v.x * v.x + v.y * v.y + v.z * v.z + v.w * v.w;
#pragma unroll
    for (int o = 16; o > 0; o >>= 1) s += __shfl_xor_sync(0xFFFFFFFFu, s, o);

    __shared__ float red[8];
    if ((tid & 31) == 0) red[tid >> 5] = s;
    __syncthreads();
    float tot = 0.f;
#pragma unroll
    for (int i = 0; i < 8; ++i) tot += red[i];

    float scale = rsqrtf(tot * (1.0f / HDIM) + 1e-6f);
    float4 w = nw[tid];
    float4 o4 = make_float4(v.x * scale * w.x, v.y * scale * w.y,
                            v.z * scale * w.z, v.w * scale * w.w);
    out[(size_t)row * (HDIM / 4) + tid] = o4;
}

// ---------------------------------------------------------------------------
// Launcher
// ---------------------------------------------------------------------------
extern "C" void kernel_launch(void* const* d_in, const int* in_sizes, int n_in,
                              void* d_out, int out_size) {
    const float* x  = (const float*)d_in[0];
    const float* cw = (const float*)d_in[1];
    const float* nw = (const float*)d_in[2];
    float* out = (float*)d_out;

    const int H  = in_sizes[2];              // 1024
    const int M  = in_sizes[0] / H;          // 16384
    const int HH = H * H;
    const int L  = in_sizes[1] / HH;         // 20

    // 1) reduce conv_w over L, scale by 1/L, store fp16
    {
        int hh4 = HH / 4;
        reduce_w_kernel<<<(hh4 + 255) / 256, 256>>>(
            (const float4*)cw, L, hh4, 1.0f / (float)L);
    }
    // 2) x -> fp16
    {
        int n4 = (M * H) / 4;
        convert_x_kernel<<<(n4 + 255) / 256, 256>>>((const float4*)x, n4);
    }
    // 3) GEMM
    {
        dim3 grid(H / BN, M / BM);
        gemm_f16_kernel<<<grid, 256>>>(M, H, H);
    }
    // 4) RMSNorm
    {
        rmsnorm_kernel<<<M, 256>>>((const float4*)nw, (float4*)out);
    }
}

// round 4
// speedup vs baseline: 1.8574x; 1.8574x over previous
#include <cuda_runtime.h>
#include <cuda_fp16.h>
#include <cstdint>

// Problem dims (fixed for this dataset entry)
// x: [B*S=16384, H=1024] fp32 ; conv_w: [L=20, H, H] ; norm_w: [H]
#define HDIM 1024
#define MDIM 16384

#if defined(__CUDA_ARCH_FEAT_SM103_ALL) || defined(__CUDA_ARCH_FEAT_SM100_ALL)
#define HAS_TCGEN05 1
#else
#define HAS_TCGEN05 0
#endif

// Scratch (allocation-free rule: __device__ globals)
__device__ __align__(256) __half g_Wh[HDIM * HDIM];          // reduced weights fp16, [o][i]
__device__ __align__(256) __half g_xh[(size_t)MDIM * HDIM];  // x in fp16
__device__ __align__(256) __half g_yh[(size_t)MDIM * HDIM];  // GEMM output (pre-norm), fp16

// ---------------------------------------------------------------------------
// Kernel 1: W[o,i] = (sum_l conv_w[l,o,i]) / L   -> fp16
// ---------------------------------------------------------------------------
__global__ void reduce_w_kernel(const float4* __restrict__ w, int L, int HH4, float inv_l) {
    int idx = blockIdx.x * blockDim.x + threadIdx.x;
    if (idx >= HH4) return;
    float4 s = make_float4(0.f, 0.f, 0.f, 0.f);
    for (int l = 0; l < L; ++l) {
        float4 v = w[(size_t)l * HH4 + idx];
        s.x += v.x; s.y += v.y; s.z += v.z; s.w += v.w;
    }
    __half2* out = reinterpret_cast<__half2*>(g_Wh);
    out[2 * idx]     = __floats2half2_rn(s.x * inv_l, s.y * inv_l);
    out[2 * idx + 1] = __floats2half2_rn(s.z * inv_l, s.w * inv_l);
}

// ---------------------------------------------------------------------------
// Kernel 2: x fp32 -> fp16
// ---------------------------------------------------------------------------
__global__ void convert_x_kernel(const float4* __restrict__ x, int n4) {
    int idx = blockIdx.x * blockDim.x + threadIdx.x;
    if (idx >= n4) return;
    float4 v = x[idx];
    __half2* out = reinterpret_cast<__half2*>(g_xh);
    out[2 * idx]     = __floats2half2_rn(v.x, v.y);
    out[2 * idx + 1] = __floats2half2_rn(v.z, v.w);
}

// ---------------------------------------------------------------------------
// Shared helpers
// ---------------------------------------------------------------------------
__device__ __forceinline__ void cp16(uint32_t sp, const void* gp) {
    asm volatile("cp.async.cg.shared.global [%0], [%1], 16;\n" :: "r"(sp), "l"(gp));
}

// GEMM tile config (both paths): CTA tile 128x128, grid (H/128, M/128), 256 thr
#define GBM 128
#define GBN 128
#define GEMM_SMEM_BYTES 66560

#if HAS_TCGEN05
// ======================== tcgen05 path (sm_103a) ===========================
#define BKH 64                    // halfs per K chunk (128 bytes, one SW128 atom row)
#define NCHUNK (HDIM / BKH)       // 16
#define TC_A_STAGE (GBM * 128)    // 16KB
#define TC_B_STAGE (GBN * 128)    // 16KB
#define TC_TILES_OFF 1024
#define TC_SMEM_A(s) (TC_TILES_OFF + (s) * TC_A_STAGE)
#define TC_SMEM_B(s) (TC_TILES_OFF + 2 * TC_A_STAGE + (s) * TC_B_STAGE)
#define SMEM_TMEM_PTR 0
#define SMEM_MBAR0 64
#define SMEM_MBAR1 80
#define TMEM_NCOLS 128
// idesc: kind::f16, dtype=F32 (bit4), atype=btype=F16(0), N=128, M=128
#define GEMM_IDESC ((1u << 4) | ((GBN / 8) << 17) | ((GBM / 16) << 24))

__device__ __forceinline__ uint64_t make_desc_sw128(uint32_t addr) {
    uint64_t d = ((uint64_t)2 << 61) | ((uint64_t)1 << 46) |
                 ((uint64_t)64 << 32) | ((uint64_t)1 << 16);
    return d | ((uint64_t)(addr >> 4) & 0x3FFF);
}

__device__ __forceinline__ void mbar_init(uint32_t a, uint32_t cnt) {
    asm volatile("mbarrier.init.shared.b64 [%0], %1;" :: "r"(a), "r"(cnt) : "memory");
}

__device__ __forceinline__ void mbar_wait(uint32_t a, uint32_t parity) {
    uint32_t done;
    asm volatile(
        "{\n\t.reg .pred p;\n\t"
        "mbarrier.try_wait.parity.acquire.cta.shared::cta.b64 p, [%1], %2;\n\t"
        "selp.b32 %0, 1, 0, p;\n\t}"
        : "=r"(done) : "r"(a), "r"(parity) : "memory");
    if (!done) {
        asm volatile(
            "{\n\t.reg .pred P1;\n\t"
            "WL_%=:\n\t"
            "mbarrier.try_wait.parity.acquire.cta.shared::cta.b64 P1, [%0], %1, 0x989680;\n\t"
            "@P1 bra.uni WD_%=;\n\t"
            "bra.uni WL_%=;\n\t"
            "WD_%=:\n\t}"
            :: "r"(a), "r"(parity) : "memory");
    }
}

__device__ __forceinline__ void tc_mma_f16_ss(uint32_t d, uint64_t ad, uint64_t bd,
                                              uint32_t idesc, uint32_t en) {
    asm volatile(
        "{\n\t.reg .pred p;\n\t"
        "setp.ne.u32 p, %5, 0;\n\t"
        "tcgen05.mma.cta_group::1.kind::f16 [%0], %1, %2, %3, {%4, %4, %4, %4}, p;\n\t"
        "}"
        :: "r"(d), "l"(ad), "l"(bd), "r"(idesc), "r"(0u), "r"(en) : "memory");
}

__device__ __forceinline__ void tc_load_stage(char* smem, int s,
                                              int m0, int n0, int kc, int tid) {
    uint32_t aBase = (uint32_t)__cvta_generic_to_shared(smem + TC_SMEM_A(s));
    uint32_t bBase = (uint32_t)__cvta_generic_to_shared(smem + TC_SMEM_B(s));
    const char* gA = (const char*)(g_xh + (size_t)m0 * HDIM) + kc * 128;
    const char* gB = (const char*)(g_Wh + (size_t)n0 * HDIM) + kc * 128;
#pragma unroll
    for (int it = 0; it < 4; ++it) {         // A: 128 rows * 8 chunks = 1024 ops
        int idx = tid + it * 256;
        int row = idx >> 3, i = idx & 7;
        uint32_t off = (uint32_t)(row * 128 + i * 16);
        off ^= ((off >> 3) & 0x70);
        cp16(aBase + off, gA + (size_t)row * 2048 + i * 16);
    }
#pragma unroll
    for (int it = 0; it < 4; ++it) {         // B: 128 rows * 8 chunks
        int idx = tid + it * 256;
        int row = idx >> 3, i = idx & 7;
        uint32_t off = (uint32_t)(row * 128 + i * 16);
        off ^= ((off >> 3) & 0x70);
        cp16(bBase + off, gB + (size_t)row * 2048 + i * 16);
    }
    asm volatile("cp.async.commit_group;\n" ::: "memory");
}

__global__ __launch_bounds__(256) void gemm_kernel() {
    extern __shared__ char smem[];
    uint32_t smem_base = (uint32_t)__cvta_generic_to_shared(smem);
    const int tid  = threadIdx.x;
    const int wid  = tid >> 5;
    const int lane = tid & 31;
    const int m0 = blockIdx.y * GBM;
    const int n0 = blockIdx.x * GBN;

    if (wid == 0) {
        asm volatile("tcgen05.alloc.cta_group::1.sync.aligned.shared::cta.b32 [%0], %1;"
                     :: "r"(smem_base + SMEM_TMEM_PTR), "r"((uint32_t)TMEM_NCOLS) : "memory");
        asm volatile("tcgen05.relinquish_alloc_permit.cta_group::1.sync.aligned;");
    }
    if (tid == 0) {
        mbar_init(smem_base + SMEM_MBAR0, 1);
        mbar_init(smem_base + SMEM_MBAR1, 1);
    }
    __syncthreads();
    uint32_t tmem_base;
    asm volatile("ld.shared.b32 %0, [%1];" : "=r"(tmem_base) : "r"(smem_base + SMEM_TMEM_PTR));

    tc_load_stage(smem, 0, m0, n0, 0, tid);
    tc_load_stage(smem, 1, m0, n0, 1, tid);

    uint32_t ph[2] = {0u, 0u};

    for (int c = 0; c < NCHUNK; ++c) {
        const int s = c & 1;
        if (c < NCHUNK - 1)
            asm volatile("cp.async.wait_group 1;\n" ::: "memory");
        else
            asm volatile("cp.async.wait_group 0;\n" ::: "memory");
        asm volatile("fence.proxy.async.shared::cta;" ::: "memory");
        __syncthreads();

        if (tid == 0) {
            uint64_t ad = make_desc_sw128(smem_base + TC_SMEM_A(s));
            uint64_t bd = make_desc_sw128(smem_base + TC_SMEM_B(s));
#pragma unroll
            for (int k = 0; k < 4; ++k) {
                uint32_t en = (c > 0 || k > 0) ? 1u : 0u;
                tc_mma_f16_ss(tmem_base, ad + k * 2, bd + k * 2, GEMM_IDESC, en);
            }
            uint32_t mb = smem_base + (s ? SMEM_MBAR1 : SMEM_MBAR0);
            asm volatile(
                "tcgen05.commit.cta_group::1.mbarrier::arrive::one.shared::cluster.b64 [%0];"
                :: "r"(mb) : "memory");
        }

        if (c + 2 < NCHUNK) {
            mbar_wait(smem_base + (s ? SMEM_MBAR1 : SMEM_MBAR0), ph[s]);
            ph[s] ^= 1;
            tc_load_stage(smem, s, m0, n0, c + 2, tid);
        }
    }

    mbar_wait(smem_base + SMEM_MBAR0, ph[0]);
    mbar_wait(smem_base + SMEM_MBAR1, ph[1]);
    asm volatile("tcgen05.fence::after_thread_sync;" ::: "memory");

    // Epilogue: 8 warps; warp w reads lanes (w&3)*32.., cols (w>>2)*64..+64
    const int row = m0 + (wid & 3) * 32 + lane;
    const int cb  = (wid >> 2) * 64;
    __half* Crow = g_yh + (size_t)row * HDIM + n0 + cb;
#pragma unroll
    for (int b = 0; b < 64; b += 32) {
        uint32_t r[32];
        asm volatile(
            "tcgen05.ld.sync.aligned.32x32b.x32.b32 "
            "{%0,%1,%2,%3,%4,%5,%6,%7,%8,%9,%10,%11,%12,%13,%14,%15,"
            "%16,%17,%18,%19,%20,%21,%22,%23,%24,%25,%26,%27,%28,%29,%30,%31}, [%32];"
            : "=r"(r[0]), "=r"(r[1]), "=r"(r[2]), "=r"(r[3]),
              "=r"(r[4]), "=r"(r[5]), "=r"(r[6]), "=r"(r[7]),
              "=r"(r[8]), "=r"(r[9]), "=r"(r[10]), "=r"(r[11]),
              "=r"(r[12]), "=r"(r[13]), "=r"(r[14]), "=r"(r[15]),
              "=r"(r[16]), "=r"(r[17]), "=r"(r[18]), "=r"(r[19]),
              "=r"(r[20]), "=r"(r[21]), "=r"(r[22]), "=r"(r[23]),
              "=r"(r[24]), "=r"(r[25]), "=r"(r[26]), "=r"(r[27]),
              "=r"(r[28]), "=r"(r[29]), "=r"(r[30]), "=r"(r[31])
            : "r"(tmem_base + cb + b));
        asm volatile("tcgen05.wait::ld.sync.aligned;" ::: "memory");
#pragma unroll
        for (int j = 0; j < 32; j += 2) {
            __half2 h = __floats2half2_rn(__uint_as_float(r[j]), __uint_as_float(r[j + 1]));
            *reinterpret_cast<__half2*>(Crow + b + j) = h;
        }
    }

    __syncthreads();
    if (wid == 0) {
        asm volatile("tcgen05.dealloc.cta_group::1.sync.aligned.b32 %0, %1;"
                     :: "r"(tmem_base), "r"((uint32_t)TMEM_NCOLS));
    }
}

#else
// ================= mma.sync fallback (base sm_103 features) ================
// 128x128x32 tile, 8 warps (4x2, warp tile 32x64), 4-stage cp.async,
// SW64 swizzle (64B rows), fragment double-buffering.
#define BK 32
#define NSTAGE 4
#define STAGE_BYTES (128 * 64)        // 8KB per operand per stage
#define FB_A(s) ((s) * STAGE_BYTES)
#define FB_B(s) (NSTAGE * STAGE_BYTES + (s) * STAGE_BYTES)

__device__ __forceinline__ uint32_t sw64(uint32_t off) {
    return off ^ ((off >> 3) & 0x30);
}

__device__ __forceinline__ void ldmx4(uint32_t& r0, uint32_t& r1, uint32_t& r2, uint32_t& r3,
                                      uint32_t addr) {
    asm volatile("ldmatrix.sync.aligned.m8n8.x4.shared.b16 {%0,%1,%2,%3}, [%4];"
                 : "=r"(r0), "=r"(r1), "=r"(r2), "=r"(r3) : "r"(addr));
}

__device__ __forceinline__ void mma16816(float* c, const uint32_t* a, const uint32_t* b) {
    asm volatile(
        "mma.sync.aligned.m16n8k16.row.col.f32.f16.f16.f32 "
        "{%0,%1,%2,%3}, {%4,%5,%6,%7}, {%8,%9}, {%0,%1,%2,%3};"
        : "+f"(c[0]), "+f"(c[1]), "+f"(c[2]), "+f"(c[3])
        : "r"(a[0]), "r"(a[1]), "r"(a[2]), "r"(a[3]), "r"(b[0]), "r"(b[1]));
}

__device__ __forceinline__ void fb_load_stage(char* smem, int s,
                                              int m0, int n0, int kt, int tid) {
    uint32_t aBase = (uint32_t)__cvta_generic_to_shared(smem + FB_A(s));
    uint32_t bBase = (uint32_t)__cvta_generic_to_shared(smem + FB_B(s));
    const char* gA = (const char*)(g_xh + (size_t)m0 * HDIM) + kt * 64;
    const char* gB = (const char*)(g_Wh + (size_t)n0 * HDIM) + kt * 64;
#pragma unroll
    for (int it = 0; it < 2; ++it) {       // 128 rows * 4 chunks = 512 ops
        int idx = tid + it * 256;
        int row = idx >> 2, c = idx & 3;
        uint32_t off = sw64((uint32_t)(row * 64 + c * 16));
        cp16(aBase + off, gA + (size_t)row * 2048 + c * 16);
    }
#pragma unroll
    for (int it = 0; it < 2; ++it) {
        int idx = tid + it * 256;
        int row = idx >> 2, c = idx & 3;
        uint32_t off = sw64((uint32_t)(row * 64 + c * 16));
        cp16(bBase + off, gB + (size_t)row * 2048 + c * 16);
    }
    asm volatile("cp.async.commit_group;\n" ::: "memory");
}

// Load one kk's fragments for this warp from stage s.
__device__ __forceinline__ void fb_load_frags(char* smem, int s, int kk,
                                              int wm, int wn, int lane,
                                              uint32_t afr[2][4], uint32_t bfr[8][2]) {
    uint32_t aBase = (uint32_t)__cvta_generic_to_shared(smem + FB_A(s));
    uint32_t bBase = (uint32_t)__cvta_generic_to_shared(smem + FB_B(s));
#pragma unroll
    for (int mt = 0; mt < 2; ++mt) {
        int row = wm * 32 + mt * 16 + (lane & 15);
        int colB = kk * 32 + (lane >> 4) * 16;
        uint32_t ad = aBase + sw64((uint32_t)(row * 64 + colB));
        ldmx4(afr[mt][0], afr[mt][1], afr[mt][2], afr[mt][3], ad);
    }
#pragma unroll
    for (int pj = 0; pj < 4; ++pj) {
        int row = wn * 64 + pj * 16 + (lane >> 4) * 8 + (lane & 7);
        int colB = kk * 32 + (((lane >> 3) & 1)) * 16;
        uint32_t ad = bBase + sw64((uint32_t)(row * 64 + colB));
        uint32_t r0, r1, r2, r3;
        ldmx4(r0, r1, r2, r3, ad);
        bfr[2 * pj][0] = r0; bfr[2 * pj][1] = r1;
        bfr[2 * pj + 1][0] = r2; bfr[2 * pj + 1][1] = r3;
    }
}

__global__ __launch_bounds__(256) void gemm_kernel() {
    extern __shared__ char smem[];
    const int tid  = threadIdx.x;
    const int lane = tid & 31;
    const int warp = tid >> 5;
    const int wm = warp >> 1;   // 0..3 : 32-row slab
    const int wn = warp & 1;    // 0..1 : 64-col slab
    const int m0 = blockIdx.y * GBM;
    const int n0 = blockIdx.x * GBN;

    float acc[2][8][4];
#pragma unroll
    for (int mt = 0; mt < 2; ++mt)
#pragma unroll
        for (int nt = 0; nt < 8; ++nt)
#pragma unroll
            for (int i = 0; i < 4; ++i) acc[mt][nt][i] = 0.f;

    const int KT = HDIM / BK;  // 32

    fb_load_stage(smem, 0, m0, n0, 0, tid);
    fb_load_stage(smem, 1, m0, n0, 1, tid);
    fb_load_stage(smem, 2, m0, n0, 2, tid);

    uint32_t afr[2][2][4];
    uint32_t bfr[2][8][2];

    for (int kt = 0; kt < KT; ++kt) {
        const int s = kt & 3;
        asm volatile("cp.async.wait_group %0;\n" :: "n"(2) : "memory");
        __syncthreads();

        fb_load_frags(smem, s, 0, wm, wn, lane, afr[0], bfr[0]);
#pragma unroll
        for (int kk = 0; kk < 2; ++kk) {
            if (kk == 0)
                fb_load_frags(smem, s, 1, wm, wn, lane, afr[1], bfr[1]);
#pragma unroll
            for (int mt = 0; mt < 2; ++mt)
#pragma unroll
                for (int nt = 0; nt < 8; ++nt)
                    mma16816(acc[mt][nt], afr[kk][mt], bfr[kk][nt]);
        }

        __syncthreads();
        if (kt + 3 < KT) fb_load_stage(smem, (kt + 3) & 3, m0, n0, kt + 3, tid);
    }

    // Epilogue: write fp16 y
#pragma unroll
    for (int mt = 0; mt < 2; ++mt) {
#pragma unroll
        for (int nt = 0; nt < 8; ++nt) {
            int row = m0 + wm * 32 + mt * 16 + (lane >> 2);
            int col = n0 + wn * 64 + nt * 8 + (lane & 3) * 2;
            __half2 h0 = __floats2half2_rn(acc[mt][nt][0], acc[mt][nt][1]);
            __half2 h1 = __floats2half2_rn(acc[mt][nt][2], acc[mt][nt][3]);
            *reinterpret_cast<__half2*>(g_yh + (size_t)row * HDIM + col) = h0;
            *reinterpret_cast<__half2*>(g_yh + (size_t)(row + 8) * HDIM + col) = h1;
        }
    }
}
#endif  // HAS_TCGEN05

// ---------------------------------------------------------------------------
// Kernel 4: RMSNorm per row of 1024 (fp16 y in, fp32 out), 256 threads/row
// ---------------------------------------------------------------------------
__global__ __launch_bounds__(256) void rmsnorm_kernel(const float4* __restrict__ nw,
                                                      float4* __restrict__ out) {
    const int row = blockIdx.x;
    const int tid = threadIdx.x;
    const uint2* yr = reinterpret_cast<const uint2*>(g_yh + (size_t)row * HDIM);

    uint2 u = yr[tid];
    __half2 h0 = *reinterpret_cast<__half2*>(&u.x);
    __half2 h1 = *reinterpret_cast<__half2*>(&u.y);
    float2 f0 = __half22float2(h0);
    float2 f1 = __half22float2(h1);
    float s = f0.x * f0.x + f0.y * f0.y + f1.x * f1.x + f1.y * f1.y;
#pragma unroll
    for (int o = 16; o > 0; o >>= 1) s += __shfl_xor_sync(0xFFFFFFFFu, s, o);

    __shared__ float red[8];
    if ((tid & 31) == 0) red[tid >> 5] = s;
    __syncthreads();
    float tot = 0.f;
#pragma unroll
    for (int i = 0; i < 8; ++i) tot += red[i];

    float scale = rsqrtf(tot * (1.0f / HDIM) + 1e-6f);
    float4 w = nw[tid];
    float4 o4 = make_float4(f0.x * scale * w.x, f0.y * scale * w.y,
                            f1.x * scale * w.z, f1.y * scale * w.w);
    out[(size_t)row * (HDIM / 4) + tid] = o4;
}

// ---------------------------------------------------------------------------
// Launcher
// ---------------------------------------------------------------------------
extern "C" void kernel_launch(void* const* d_in, const int* in_sizes, int n_in,
                              void* d_out, int out_size) {
    const float* x  = (const float*)d_in[0];
    const float* cw = (const float*)d_in[1];
    const float* nw = (const float*)d_in[2];
    float* out = (float*)d_out;

    const int H  = in_sizes[2];              // 1024
    const int M  = in_sizes[0] / H;          // 16384
    const int HH = H * H;
    const int L  = in_sizes[1] / HH;         // 20

    // 1) reduce conv_w over L, scale by 1/L, store fp16
    {
        int hh4 = HH / 4;
        reduce_w_kernel<<<(hh4 + 255) / 256, 256>>>(
            (const float4*)cw, L, hh4, 1.0f / (float)L);
    }
    // 2) x -> fp16
    {
        int n4 = (M * H) / 4;
        convert_x_kernel<<<(n4 + 255) / 256, 256>>>((const float4*)x, n4);
    }
    // 3) GEMM (tcgen05 if arch-specific features compiled, else mma.sync)
    {
        static bool attr_set = false;
        if (!attr_set) {
            cudaFuncSetAttribute(gemm_kernel,
                                 cudaFuncAttributeMaxDynamicSharedMemorySize,
                                 GEMM_SMEM_BYTES);
            attr_set = true;
        }
        dim3 grid(H / GBN, M / GBM);
        gemm_kernel<<<grid, 256, GEMM_SMEM_BYTES>>>();
    }
    // 4) RMSNorm
    {
        rmsnorm_kernel<<<M, 256>>>((const float4*)nw, (float4*)out);
    }
}